// round 9
// baseline (speedup 1.0000x reference)
#include <cuda_runtime.h>
#include <cstdint>

// Problem constants (match reference)
#define FEAT_W   32
#define FEAT_H   32
#define HW       1024          // 32*32
#define M_GT     64
#define GT_STRIDE 14

// Output tensor offsets in floats. BN = 4096; slab = BN*HW floats.
#define SLAB     4194304ll
#define OFF_CLS   (0ll)
#define OFF_CLSW  (SLAB*1)
#define OFF_R2    (SLAB*2)
#define OFF_R2W   (SLAB*4)
#define OFF_R3    (SLAB*6)
#define OFF_R3W   (SLAB*8)
#define OFF_DL    (SLAB*10)
#define OFF_DLW   (SLAB*11)
#define OFF_DIM   (SLAB*12)
#define OFF_DIMW  (SLAB*15)
#define OFF_ROT   (SLAB*18)
#define OFF_ROTW  (SLAB*19)

// Default write-back store: dirty lines keep normal L2 priority; lines still
// resident at the next graph replay are overwritten in L2 without a DRAM
// writeback (best measured variant, R8).
__device__ __forceinline__ void st4(float* p, float a, float b, float c, float d) {
    float4 v = make_float4(a, b, c, d);
    *reinterpret_cast<float4*>(p) = v;
}

// Two CTAs per box (half the 32x32 map each): halves T_CTA so the end-of-kernel
// drain tail and wave-quantization raggedness shrink, at identical warp count
// per SM (16 CTAs x 4 warps = 64 warps) and identical per-thread work.
__global__ __launch_bounds__(128, 16)
void rcnn3d_label_kernel(const float* __restrict__ boxes,
                         const float* __restrict__ gt_boxes,
                         const int*   __restrict__ match_pos_flag,
                         const int*   __restrict__ match_gt_id,
                         float*       __restrict__ out)
{
    const int bn   = blockIdx.x >> 1;      // box id 0..4095  (b*N + n)
    const int half = blockIdx.x & 1;       // 0: rows 0-15, 1: rows 16-31
    const int b    = bn >> 10;
    const int tid  = threadIdx.x;          // 0..127, one float4 of pixels

    __shared__ __align__(16) float exs[FEAT_W];
    __shared__ __align__(16) float eys[FEAT_H];   // full table (has-consistency)

    // ---- per-box scalars (uniform; broadcast loads) ----
    const float x1 = __ldg(boxes + (size_t)bn * 4 + 0);
    const float y1 = __ldg(boxes + (size_t)bn * 4 + 1);
    const float x2 = __ldg(boxes + (size_t)bn * 4 + 2);
    const float y2 = __ldg(boxes + (size_t)bn * 4 + 3);
    const int gid  = __ldg(match_gt_id + bn);
    const int flag = __ldg(match_pos_flag + bn);

    const float* g = gt_boxes + ((size_t)b * M_GT + gid) * GT_STRIDE;
    const float kxg   = __ldg(g + 4);
    const float kyg   = __ldg(g + 5);
    const float vis   = __ldg(g + 6);
    const float dim0  = __ldg(g + 7);
    const float dim1  = __ldg(g + 8);
    const float dim2  = __ldg(g + 9);
    const float depth = __ldg(g + 12);
    const float rot   = __ldg(g + 13);

    const float cx = 0.5f * (x1 + x2);
    const float cy = 0.5f * (y1 + y2);
    const float hw = 0.5f * (x2 - x1) * 1.2f;   // EXPAND
    const float hh = 0.5f * (y2 - y1) * 1.2f;
    const float ex1 = cx - hw, ex2 = cx + hw;
    const float ey1 = cy - hh, ey2 = cy + hh;
    const float sx = (float)FEAT_W / (ex2 - ex1 + 1.0f);
    const float sy = (float)FEAT_H / (ey2 - ey1 + 1.0f);
    const float kx = (kxg - ex1) * sx;
    const float ky = (kyg - ey1) * sy;
    const bool valid = (vis != 0.0f) && (flag > 0);

    // ---- separable Gaussian tables (full x and y): 64 expf per CTA ----
    if (tid < FEAT_W) {
        const float d = (float)tid + 0.5f - kx;
        exs[tid] = expf(-(d * d) / 5.12f);       // 2*SIGMA^2
    } else if (tid < FEAT_W + FEAT_H) {
        const int r = tid - FEAT_W;
        const float d = (float)r + 0.5f - ky;
        eys[r] = expf(-(d * d) / 5.12f);
    }
    __syncthreads();

    // ---- analytic 'has': peak of exs[gx]*eys[gy] at clamped-nearest cell ----
    int ixn = __float2int_rn(kx - 0.5f); ixn = min(FEAT_W - 1, max(0, ixn));
    int iyn = __float2int_rn(ky - 0.5f); iyn = min(FEAT_H - 1, max(0, iyn));
    const float smax = exs[ixn] * eys[iyn];
    const bool  has  = valid && (smax >= 0.6f);
    const float hasf = has ? 1.0f : 0.0f;

    // ---- this thread's 4 pixels: global row gy, cols gx0..gx0+3 ----
    const int gy  = (tid >> 3) + (half << 4);   // 16 rows per CTA half
    const int gx0 = (tid & 7) << 2;
    const float ey   = eys[gy];
    const float offy = ky - (float)gy;
    const float4 exv = reinterpret_cast<const float4*>(exs)[tid & 7];
    const float exa[4] = {exv.x, exv.y, exv.z, exv.w};

    float sc[4], offx[4], m2f[4], m3f[4];
#pragma unroll
    for (int j = 0; j < 4; ++j) {
        const float gx = (float)(gx0 + j);
        sc[j]   = exa[j] * ey;
        offx[j] = kx - gx;
        m2f[j] = (valid && sc[j] >= 0.6f) ? 1.0f : 0.0f;
        m3f[j] = (valid && sc[j] >= 0.5f) ? 1.0f : 0.0f;   // depth thr == 3d thr
    }

    // ---- 20 coalesced float4 stores, default .wb policy ----
    const long long pix  = (long long)(half * 512 + tid * 4);  // gy*32 + gx0
    const long long base = (long long)bn * HW + pix;
    const long long b2c  = (long long)bn * 2 * HW + pix;
    const long long b3c  = (long long)bn * 3 * HW + pix;

    if (has) st4(out + OFF_CLS + base, sc[0], sc[1], sc[2], sc[3]);
    else     st4(out + OFF_CLS + base, -1.0f, -1.0f, -1.0f, -1.0f);
    st4(out + OFF_CLSW + base, hasf, hasf, hasf, hasf);

    st4(out + OFF_R2  + b2c,      offx[0]*m2f[0], offx[1]*m2f[1], offx[2]*m2f[2], offx[3]*m2f[3]);
    st4(out + OFF_R2  + b2c + HW, offy*m2f[0],    offy*m2f[1],    offy*m2f[2],    offy*m2f[3]);
    st4(out + OFF_R2W + b2c,      m2f[0], m2f[1], m2f[2], m2f[3]);
    st4(out + OFF_R2W + b2c + HW, m2f[0], m2f[1], m2f[2], m2f[3]);

    st4(out + OFF_R3  + b2c,      offx[0]*m3f[0], offx[1]*m3f[1], offx[2]*m3f[2], offx[3]*m3f[3]);
    st4(out + OFF_R3  + b2c + HW, offy*m3f[0],    offy*m3f[1],    offy*m3f[2],    offy*m3f[3]);
    st4(out + OFF_R3W + b2c,      m3f[0], m3f[1], m3f[2], m3f[3]);
    st4(out + OFF_R3W + b2c + HW, m3f[0], m3f[1], m3f[2], m3f[3]);

    st4(out + OFF_DL  + base, depth*m3f[0], depth*m3f[1], depth*m3f[2], depth*m3f[3]);
    st4(out + OFF_DLW + base, m3f[0], m3f[1], m3f[2], m3f[3]);

    st4(out + OFF_DIM  + b3c,        dim0*m3f[0], dim0*m3f[1], dim0*m3f[2], dim0*m3f[3]);
    st4(out + OFF_DIM  + b3c + HW,   dim1*m3f[0], dim1*m3f[1], dim1*m3f[2], dim1*m3f[3]);
    st4(out + OFF_DIM  + b3c + 2*HW, dim2*m3f[0], dim2*m3f[1], dim2*m3f[2], dim2*m3f[3]);
    st4(out + OFF_DIMW + b3c,        m3f[0], m3f[1], m3f[2], m3f[3]);
    st4(out + OFF_DIMW + b3c + HW,   m3f[0], m3f[1], m3f[2], m3f[3]);
    st4(out + OFF_DIMW + b3c + 2*HW, m3f[0], m3f[1], m3f[2], m3f[3]);

    st4(out + OFF_ROT  + base, rot*m3f[0], rot*m3f[1], rot*m3f[2], rot*m3f[3]);
    st4(out + OFF_ROTW + base, m3f[0], m3f[1], m3f[2], m3f[3]);
}

extern "C" void kernel_launch(void* const* d_in, const int* in_sizes, int n_in,
                              void* d_out, int out_size) {
    const float* boxes          = (const float*)d_in[0];
    const float* gt_boxes       = (const float*)d_in[1];
    const int*   match_pos_flag = (const int*)d_in[2];
    const int*   match_gt_id    = (const int*)d_in[3];
    float* out = (float*)d_out;

    // Two 128-thread CTAs per box: 8192 CTAs, 16 CTAs/SM (64 warps/SM), finer
    // end-of-kernel drain granularity at the LTS-cap-bound store roofline.
    rcnn3d_label_kernel<<<8192, 128>>>(boxes, gt_boxes, match_pos_flag,
                                       match_gt_id, out);
}

// round 10
// speedup vs baseline: 1.3554x; 1.3554x over previous
#include <cuda_runtime.h>
#include <cstdint>

// Problem constants (match reference)
#define FEAT_W   32
#define FEAT_H   32
#define HW       1024          // 32*32
#define M_GT     64
#define GT_STRIDE 14

// Output tensor offsets in floats. BN = 4096; slab = BN*HW floats.
#define SLAB     4194304ll
#define OFF_CLS   (0ll)
#define OFF_CLSW  (SLAB*1)
#define OFF_R2    (SLAB*2)
#define OFF_R2W   (SLAB*4)
#define OFF_R3    (SLAB*6)
#define OFF_R3W   (SLAB*8)
#define OFF_DL    (SLAB*10)
#define OFF_DLW   (SLAB*11)
#define OFF_DIM   (SLAB*12)
#define OFF_DIMW  (SLAB*15)
#define OFF_ROT   (SLAB*18)
#define OFF_ROTW  (SLAB*19)

// Default write-back store: best measured policy (R8). Dirty lines keep normal
// L2 priority; lines still resident at the next graph replay are overwritten
// in L2 without costing a DRAM writeback.
__device__ __forceinline__ void st4(float* p, float a, float b, float c, float d) {
    float4 v = make_float4(a, b, c, d);
    *reinterpret_cast<float4*>(p) = v;
}

// One 256-thread CTA per box: 4 KB contiguous burst per channel per CTA.
// (R9 showed that halving this burst to 2 KB across two SMs drops HBM write
// rate from 5.55 to 3.93 TB/s — burst coherence beats scheduling granularity.)
__global__ __launch_bounds__(256, 8)
void rcnn3d_label_kernel(const float* __restrict__ boxes,
                         const float* __restrict__ gt_boxes,
                         const int*   __restrict__ match_pos_flag,
                         const int*   __restrict__ match_gt_id,
                         float*       __restrict__ out)
{
    const int bn  = blockIdx.x;            // b*N + n
    const int b   = bn >> 10;
    const int tid = threadIdx.x;

    __shared__ __align__(16) float exs[FEAT_W];
    __shared__ __align__(16) float eys[FEAT_H];

    // ---- per-box scalars (uniform; broadcast loads) ----
    const float x1 = __ldg(boxes + (size_t)bn * 4 + 0);
    const float y1 = __ldg(boxes + (size_t)bn * 4 + 1);
    const float x2 = __ldg(boxes + (size_t)bn * 4 + 2);
    const float y2 = __ldg(boxes + (size_t)bn * 4 + 3);
    const int gid  = __ldg(match_gt_id + bn);
    const int flag = __ldg(match_pos_flag + bn);

    const float* g = gt_boxes + ((size_t)b * M_GT + gid) * GT_STRIDE;
    const float kxg   = __ldg(g + 4);
    const float kyg   = __ldg(g + 5);
    const float vis   = __ldg(g + 6);
    const float dim0  = __ldg(g + 7);
    const float dim1  = __ldg(g + 8);
    const float dim2  = __ldg(g + 9);
    const float depth = __ldg(g + 12);
    const float rot   = __ldg(g + 13);

    const float cx = 0.5f * (x1 + x2);
    const float cy = 0.5f * (y1 + y2);
    const float hw = 0.5f * (x2 - x1) * 1.2f;   // EXPAND
    const float hh = 0.5f * (y2 - y1) * 1.2f;
    const float ex1 = cx - hw, ex2 = cx + hw;
    const float ey1 = cy - hh, ey2 = cy + hh;
    const float sx = (float)FEAT_W / (ex2 - ex1 + 1.0f);
    const float sy = (float)FEAT_H / (ey2 - ey1 + 1.0f);
    const float kx = (kxg - ex1) * sx;
    const float ky = (kyg - ey1) * sy;
    const bool valid = (vis != 0.0f) && (flag > 0);

    // ---- separable Gaussian tables: 64 expf per CTA ----
    if (tid < FEAT_W) {
        const float d = (float)tid + 0.5f - kx;
        exs[tid] = expf(-(d * d) / 5.12f);       // 2*SIGMA^2
    } else if (tid < FEAT_W + FEAT_H) {
        const int r = tid - FEAT_W;
        const float d = (float)r + 0.5f - ky;
        eys[r] = expf(-(d * d) / 5.12f);
    }
    __syncthreads();

    // ---- analytic 'has': peak of exs[gx]*eys[gy] at clamped-nearest cell ----
    int ixn = __float2int_rn(kx - 0.5f); ixn = min(FEAT_W - 1, max(0, ixn));
    int iyn = __float2int_rn(ky - 0.5f); iyn = min(FEAT_H - 1, max(0, iyn));
    const float smax = exs[ixn] * eys[iyn];
    const bool  has  = valid && (smax >= 0.6f);
    const float hasf = has ? 1.0f : 0.0f;

    // ---- this thread's 4 pixels: row gy, cols gx0..gx0+3 ----
    const int gy  = tid >> 3;
    const int gx0 = (tid & 7) << 2;
    const float ey   = eys[gy];
    const float offy = ky - (float)gy;
    const float4 exv = reinterpret_cast<const float4*>(exs)[tid & 7];
    const float exa[4] = {exv.x, exv.y, exv.z, exv.w};

    float cls[4], offx[4], m2f[4], m3f[4];
#pragma unroll
    for (int j = 0; j < 4; ++j) {
        const float gx = (float)(gx0 + j);
        const float sc = exa[j] * ey;
        offx[j] = kx - gx;
        m2f[j] = (valid && sc >= 0.6f) ? 1.0f : 0.0f;
        m3f[j] = (valid && sc >= 0.5f) ? 1.0f : 0.0f;   // depth thr == 3d thr
        cls[j] = has ? sc : -1.0f;                      // branchless (SELP)
    }

    // ---- 20 coalesced float4 stores, default .wb policy ----
    const long long pix  = (long long)tid * 4;
    const long long base = (long long)bn * HW + pix;
    const long long b2c  = (long long)bn * 2 * HW + pix;
    const long long b3c  = (long long)bn * 3 * HW + pix;

    st4(out + OFF_CLS  + base, cls[0], cls[1], cls[2], cls[3]);
    st4(out + OFF_CLSW + base, hasf, hasf, hasf, hasf);

    st4(out + OFF_R2  + b2c,      offx[0]*m2f[0], offx[1]*m2f[1], offx[2]*m2f[2], offx[3]*m2f[3]);
    st4(out + OFF_R2  + b2c + HW, offy*m2f[0],    offy*m2f[1],    offy*m2f[2],    offy*m2f[3]);
    st4(out + OFF_R2W + b2c,      m2f[0], m2f[1], m2f[2], m2f[3]);
    st4(out + OFF_R2W + b2c + HW, m2f[0], m2f[1], m2f[2], m2f[3]);

    st4(out + OFF_R3  + b2c,      offx[0]*m3f[0], offx[1]*m3f[1], offx[2]*m3f[2], offx[3]*m3f[3]);
    st4(out + OFF_R3  + b2c + HW, offy*m3f[0],    offy*m3f[1],    offy*m3f[2],    offy*m3f[3]);
    st4(out + OFF_R3W + b2c,      m3f[0], m3f[1], m3f[2], m3f[3]);
    st4(out + OFF_R3W + b2c + HW, m3f[0], m3f[1], m3f[2], m3f[3]);

    st4(out + OFF_DL  + base, depth*m3f[0], depth*m3f[1], depth*m3f[2], depth*m3f[3]);
    st4(out + OFF_DLW + base, m3f[0], m3f[1], m3f[2], m3f[3]);

    st4(out + OFF_DIM  + b3c,        dim0*m3f[0], dim0*m3f[1], dim0*m3f[2], dim0*m3f[3]);
    st4(out + OFF_DIM  + b3c + HW,   dim1*m3f[0], dim1*m3f[1], dim1*m3f[2], dim1*m3f[3]);
    st4(out + OFF_DIM  + b3c + 2*HW, dim2*m3f[0], dim2*m3f[1], dim2*m3f[2], dim2*m3f[3]);
    st4(out + OFF_DIMW + b3c,        m3f[0], m3f[1], m3f[2], m3f[3]);
    st4(out + OFF_DIMW + b3c + HW,   m3f[0], m3f[1], m3f[2], m3f[3]);
    st4(out + OFF_DIMW + b3c + 2*HW, m3f[0], m3f[1], m3f[2], m3f[3]);

    st4(out + OFF_ROT  + base, rot*m3f[0], rot*m3f[1], rot*m3f[2], rot*m3f[3]);
    st4(out + OFF_ROTW + base, m3f[0], m3f[1], m3f[2], m3f[3]);
}

extern "C" void kernel_launch(void* const* d_in, const int* in_sizes, int n_in,
                              void* d_out, int out_size) {
    const float* boxes          = (const float*)d_in[0];
    const float* gt_boxes       = (const float*)d_in[1];
    const int*   match_pos_flag = (const int*)d_in[2];
    const int*   match_gt_id    = (const int*)d_in[3];
    float* out = (float*)d_out;

    // One CTA per box (best-measured config, R8): 4096 x 256, default .wb
    // stores, 4 KB contiguous burst per channel per CTA.
    rcnn3d_label_kernel<<<4096, 256>>>(boxes, gt_boxes, match_pos_flag,
                                       match_gt_id, out);
}